// round 14
// baseline (speedup 1.0000x reference)
#include <cuda_runtime.h>
#include <cuda_bf16.h>
#include <cstdint>

// ---------------------------------------------------------------------------
// APD2Net: graph_conv == 3x3 SAME conv (weights (O,C,9), k=ky*3+kx),
// graph_pool == 2x2 maxpool. NCHW fp32 end-to-end.
//
// R14: tensor-pipe implicit GEMM (mma.sync.m16n8k8.tf32).
//  - A fragments loaded DIRECTLY from gmem (fragment-major layout) via
//    LDG.128 with one-tap-ahead register prefetch — no A smem at all.
//  - X staged k-interleaved (R13): one LDS.128 = B fragments for 4 MMAs.
//  - smem 25.9 KB, __launch_bounds__(128,3) -> 3 CTAs/SM (12 warps).
//  - fused 2x2 maxpool epilogue on conv2/conv4/conv7. conv1 stays FFMA2.
// ---------------------------------------------------------------------------

__device__ float g_bufA[2u * 64u * 384u * 384u];
__device__ float g_bufB[2u * 64u * 384u * 384u];
__device__ float g_bufW[7630848u];               // all transformed weights

__device__ __forceinline__ uint32_t f32_to_tf32(float v) {
    uint32_t t;
    asm("cvt.rna.tf32.f32 %0, %1;" : "=r"(t) : "f"(v));
    return t;
}
__device__ __forceinline__ void cp_async4(void* smem_dst, const void* gptr, int src_bytes) {
    unsigned sa = (unsigned)__cvta_generic_to_shared(smem_dst);
    asm volatile("cp.async.ca.shared.global [%0], [%1], 4, %2;\n"
                 :: "r"(sa), "l"(gptr), "r"(src_bytes));
}
__device__ __forceinline__ void cp_commit() { asm volatile("cp.async.commit_group;"); }
__device__ __forceinline__ void cp_wait1()  { asm volatile("cp.async.wait_group 1;"); }
__device__ __forceinline__ void cp_wait0()  { asm volatile("cp.async.wait_group 0;"); }

// ============================ fused weight transform ========================
// Per layer: w (COUT,CIN,9) -> fragment-major (z)(tap)(k8g)(q)(lane)(reg)
struct WXform {
    const float* src[9];
    long start[10];
    int cout[9], cin[9];
};

__global__ void transform_all(WXform p, float* __restrict__ dstbase)
{
    long gid0 = (long)blockIdx.x * blockDim.x + threadIdx.x;
    if (gid0 >= p.start[9]) return;
    int l = 0;
    #pragma unroll
    for (int i = 1; i < 9; ++i) if (gid0 >= p.start[i]) l = i;
    long i = gid0 - p.start[l];
    const int CIN = p.cin[l];
    const int K8 = CIN / 8;

    int reg  = (int)(i & 3);
    int lane = (int)((i >> 2) & 31);
    int q    = (int)((i >> 7) & 3);
    long r   = i >> 9;                 // (z*9 + t)*K8 + k8g
    int k8g  = (int)(r % K8);
    long zt  = r / K8;
    int t    = (int)(zt % 9);
    int z    = (int)(zt / 9);

    int tig = lane & 3, gidl = lane >> 2;
    int mhalf = reg & 1, khalf = reg >> 1;
    int oc = z * 64 + q * 16 + mhalf * 8 + gidl;
    int c  = k8g * 8 + khalf * 4 + tig;
    float v = p.src[l][((size_t)oc * CIN + c) * 9 + t];
    dstbase[p.start[l] + i] = __uint_as_float(f32_to_tf32(v));
}

// ============================ tensor conv ==================================
// Block 128 thr = 4 warps: warp_m = wid&1 (2 x 32oc), warp_n = wid>>1 (2 x 64px)
// CTA tile: 64 oc x 128 px (8y x 16x). KC=16, X double-buffered (cp.async).
// A fragments: direct LDG.128 from fragment-major gmem, 1-tap-ahead prefetch.
template <int CIN, int COUT, bool ROUND, bool POOL>
__global__ void __launch_bounds__(128, 3)
conv3x3_mma(const float* __restrict__ in,
            const float* __restrict__ wT,
            const float* __restrict__ bias,
            float* __restrict__ out, int H, int W)
{
    constexpr int KC = 16;
    static_assert(CIN % KC == 0, "");
    constexpr int NCH = CIN / KC;
    constexpr int NIT = NCH * 9;
    constexpr int K8 = CIN / 8;
    constexpr int XPL = 202;                   // plane pitch in 16B units
    constexpr int XSTG = 4 * XPL * 4;          // floats per X stage (3232)

    extern __shared__ float sm[];
    float* Xs = sm;                            // [2][XSTG]

    const int tid  = threadIdx.x;
    const int lane = tid & 31;
    const int wid  = tid >> 5;
    const int gid  = lane >> 2;
    const int tig  = lane & 3;
    const int warp_m = wid & 1;
    const int warp_n = wid >> 1;               // 0..1

    const int tiles_x = W / 16;
    const int bx = (blockIdx.x % tiles_x) * 16;
    const int by = (blockIdx.x / tiles_x) * 8;
    const int n_img = blockIdx.y;
    const int zsl = blockIdx.z;
    const int oc_base = zsl * 64;

    float acc[2][8][4];
    #pragma unroll
    for (int mt = 0; mt < 2; ++mt)
        #pragma unroll
        for (int nt = 0; nt < 8; ++nt)
            #pragma unroll
            for (int r = 0; r < 4; ++r) acc[mt][nt][r] = 0.0f;

    int b_y0[8], b_x[8];
    #pragma unroll
    for (int nt = 0; nt < 8; ++nt) {
        int n_base = warp_n * 64 + nt * 8;
        b_y0[nt] = n_base >> 4;
        b_x[nt]  = (n_base & 15) + gid;
    }

    // thread's A-fragment base: + (tap*K8 + 2*ch + ks)*512
    const float* wfrag = wT + (size_t)zsl * 9 * K8 * 512
                       + (warp_m * 2) * 128 + lane * 4;

    auto load_X = [&](int s, int ch) {
        const int c0 = ch * KC;
        constexpr int TOT = KC * 10 * 18;      // 2880
        float* dst = Xs + s * XSTG;
        #pragma unroll
        for (int it = 0; it < (TOT + 127) / 128; ++it) {
            int idx = it * 128 + tid;
            if (idx < TOT) {
                int c  = idx / 180;
                int r  = idx % 180;
                int yy = r / 18;
                int xx = r % 18;
                int ctig = c & 3;
                int j    = c >> 2;
                int gy = by + yy - 1;
                int gx = bx + xx - 1;
                bool ok = (gy >= 0 && gy < H && gx >= 0 && gx < W);
                const float* src = ok
                    ? in + (((size_t)n_img * CIN + c0 + c) * H + gy) * W + gx
                    : in;
                cp_async4(dst + (ctig * XPL + yy * 20 + xx) * 4 + j,
                          src, ok ? 4 : 0);
            }
        }
        cp_commit();
    };

    // ---- A prefetch: iter = ch*9 + tap
    auto a_ld = [&](int it2, float4* dstf) {
        int ch  = it2 / 9;
        int tap = it2 - ch * 9;
        #pragma unroll
        for (int ks = 0; ks < 2; ++ks)
            #pragma unroll
            for (int mt = 0; mt < 2; ++mt)
                dstf[ks * 2 + mt] = *reinterpret_cast<const float4*>(
                    wfrag + ((size_t)tap * K8 + 2 * ch + ks) * 512 + mt * 128);
    };

    float4 aN[4];
    a_ld(0, aN);
    load_X(0, 0);

    #pragma unroll 1
    for (int ch = 0; ch < NCH; ++ch) {
        const int s = ch & 1;
        if (ch + 1 < NCH) { load_X(s ^ 1, ch + 1); cp_wait1(); }
        else              { cp_wait0(); }
        __syncthreads();

        const float4* xb = reinterpret_cast<const float4*>(Xs + s * XSTG)
                         + tig * XPL;

        #pragma unroll 1
        for (int tap = 0; tap < 9; ++tap) {
            const int ky = tap / 3, kx = tap % 3;
            float4 aC[4];
            #pragma unroll
            for (int j = 0; j < 4; ++j) aC[j] = aN[j];
            int nit = ch * 9 + tap + 1;
            a_ld(nit < NIT ? nit : NIT - 1, aN);

            uint32_t a[2][2][4];
            #pragma unroll
            for (int ks = 0; ks < 2; ++ks)
                #pragma unroll
                for (int mt = 0; mt < 2; ++mt) {
                    const float4 af = aC[ks * 2 + mt];
                    a[ks][mt][0] = __float_as_uint(af.x);
                    a[ks][mt][1] = __float_as_uint(af.y);
                    a[ks][mt][2] = __float_as_uint(af.z);
                    a[ks][mt][3] = __float_as_uint(af.w);
                }
            #pragma unroll
            for (int nt = 0; nt < 8; ++nt) {
                const float4 bf = xb[(b_y0[nt] + ky) * 20 + b_x[nt] + kx];
                uint32_t b00 = __float_as_uint(bf.x);
                uint32_t b01 = __float_as_uint(bf.y);
                uint32_t b10 = __float_as_uint(bf.z);
                uint32_t b11 = __float_as_uint(bf.w);
                #pragma unroll
                for (int mt = 0; mt < 2; ++mt) {
                    float* d = acc[mt][nt];
                    asm volatile(
                        "mma.sync.aligned.m16n8k8.row.col.f32.tf32.tf32.f32 "
                        "{%0,%1,%2,%3}, {%4,%5,%6,%7}, {%8,%9}, {%0,%1,%2,%3};"
                        : "+f"(d[0]), "+f"(d[1]), "+f"(d[2]), "+f"(d[3])
                        : "r"(a[0][mt][0]), "r"(a[0][mt][1]),
                          "r"(a[0][mt][2]), "r"(a[0][mt][3]),
                          "r"(b00), "r"(b01));
                    asm volatile(
                        "mma.sync.aligned.m16n8k8.row.col.f32.tf32.tf32.f32 "
                        "{%0,%1,%2,%3}, {%4,%5,%6,%7}, {%8,%9}, {%0,%1,%2,%3};"
                        : "+f"(d[0]), "+f"(d[1]), "+f"(d[2]), "+f"(d[3])
                        : "r"(a[1][mt][0]), "r"(a[1][mt][1]),
                          "r"(a[1][mt][2]), "r"(a[1][mt][3]),
                          "r"(b10), "r"(b11));
                }
            }
        }
        __syncthreads();
    }

    // ---- epilogue
    if (POOL) {
        const int Ho = H >> 1, Wo = W >> 1;
        #pragma unroll
        for (int mt = 0; mt < 2; ++mt) {
            int oc0 = oc_base + (warp_m * 2 + mt) * 16 + gid;
            float bv0 = bias[oc0];
            float bv1 = bias[oc0 + 8];
            #pragma unroll
            for (int g = 0; g < 4; ++g) {
                int nt  = (g & 1) | ((g & 2) << 1);   // 0,1,4,5
                int ntb = nt + 2;
                float p0 = fmaxf(fmaxf(acc[mt][nt][0],  acc[mt][nt][1]),
                                 fmaxf(acc[mt][ntb][0], acc[mt][ntb][1]));
                float p1 = fmaxf(fmaxf(acc[mt][nt][2],  acc[mt][nt][3]),
                                 fmaxf(acc[mt][ntb][2], acc[mt][ntb][3]));
                p0 = fmaxf(p0 + bv0, 0.0f);
                p1 = fmaxf(p1 + bv1, 0.0f);
                if (ROUND) {
                    p0 = __uint_as_float(f32_to_tf32(p0));
                    p1 = __uint_as_float(f32_to_tf32(p1));
                }
                int px = warp_n * 64 + nt * 8 + tig * 2;
                int oy = (by + (px >> 4)) >> 1;
                int ox = (bx + (px & 15)) >> 1;
                out[(((size_t)n_img * COUT + oc0) * Ho + oy) * Wo + ox] = p0;
                out[(((size_t)n_img * COUT + oc0 + 8) * Ho + oy) * Wo + ox] = p1;
            }
        }
    } else {
        #pragma unroll
        for (int mt = 0; mt < 2; ++mt) {
            int oc0 = oc_base + (warp_m * 2 + mt) * 16 + gid;
            float bv0 = bias[oc0];
            float bv1 = bias[oc0 + 8];
            #pragma unroll
            for (int nt = 0; nt < 8; ++nt) {
                int px = warp_n * 64 + nt * 8 + tig * 2;
                int gy = by + (px >> 4);
                int gx = bx + (px & 15);
                float v00 = fmaxf(acc[mt][nt][0] + bv0, 0.0f);
                float v01 = fmaxf(acc[mt][nt][1] + bv0, 0.0f);
                float v10 = fmaxf(acc[mt][nt][2] + bv1, 0.0f);
                float v11 = fmaxf(acc[mt][nt][3] + bv1, 0.0f);
                if (ROUND) {
                    v00 = __uint_as_float(f32_to_tf32(v00));
                    v01 = __uint_as_float(f32_to_tf32(v01));
                    v10 = __uint_as_float(f32_to_tf32(v10));
                    v11 = __uint_as_float(f32_to_tf32(v11));
                }
                float* d0 = out + (((size_t)n_img * COUT + oc0) * H + gy) * W + gx;
                float* d1 = d0 + (size_t)8 * H * W;
                *reinterpret_cast<float2*>(d0) = make_float2(v00, v01);
                *reinterpret_cast<float2*>(d1) = make_float2(v10, v11);
            }
        }
    }
}

// ============================ FFMA2 conv (conv1 only) ======================
__device__ __forceinline__ unsigned long long fma2(unsigned long long a,
                                                   unsigned long long b,
                                                   unsigned long long c) {
    unsigned long long d;
    asm("fma.rn.f32x2 %0, %1, %2, %3;" : "=l"(d) : "l"(a), "l"(b), "l"(c));
    return d;
}
__device__ __forceinline__ unsigned long long dup2(float v) {
    unsigned long long d;
    asm("mov.b64 %0, {%1, %1};" : "=l"(d) : "f"(v));
    return d;
}
__device__ __forceinline__ float2 unpack2(unsigned long long v) {
    float2 r;
    asm("mov.b64 {%0, %1}, %2;" : "=f"(r.x), "=f"(r.y) : "l"(v));
    return r;
}
__device__ __host__ __forceinline__ int woff_of(int ocg) {
    return ocg * 8 + (ocg >> 2) * 2;
}

template <int CIN, int COUT, int CHUNK, int TH, int TW, bool ROUND>
__global__ void __launch_bounds__(256, 2)
conv3x3_ffma(const float* __restrict__ in,
             const float* __restrict__ wgt,
             const float* __restrict__ bias,
             float* __restrict__ out, int H, int W)
{
    constexpr int OCB = 64;
    constexpr int WROW = 68;
    constexpr int IROW = TW + 2;
    constexpr int CG = TW / 8;

    __shared__ __align__(16) float wsm[CHUNK][9][WROW];
    __shared__ float insm[CHUNK][TH + 2][IROW];

    const int tiles_x = W / TW;
    const int bx = (blockIdx.x % tiles_x) * TW;
    const int by = (blockIdx.x / tiles_x) * TH;
    const int n  = blockIdx.y;
    const int oc_base = blockIdx.z * OCB;

    const int tid = threadIdx.x;
    const int ocg = tid & 7;
    const int pg  = tid >> 3;
    const int row = pg / CG;
    const int col = (pg % CG) * 8;
    const int woff = woff_of(ocg);

    unsigned long long acc[4][8];
    #pragma unroll
    for (int op = 0; op < 4; ++op)
        #pragma unroll
        for (int p = 0; p < 8; ++p) acc[op][p] = 0ull;

    #pragma unroll 1
    for (int c0 = 0; c0 < CIN; c0 += CHUNK) {
        {
            const float* wg = wgt + (size_t)oc_base * CIN * 9 + (size_t)c0 * 9;
            constexpr int PER_OC = CHUNK * 9;
            constexpr int TOT = OCB * PER_OC;
            for (int idx = tid; idx < TOT; idx += 256) {
                int oc = idx / PER_OC;
                int r  = idx % PER_OC;
                float v = wg[(size_t)oc * CIN * 9 + r];
                wsm[r / 9][r % 9][woff_of(oc >> 3) + (oc & 7)] = v;
            }
        }
        {
            constexpr int TILE2D = (TH + 2) * IROW;
            constexpr int TOT = CHUNK * TILE2D;
            for (int idx = tid; idx < TOT; idx += 256) {
                int c   = idx / TILE2D;
                int rem = idx % TILE2D;
                int iy  = rem / IROW;
                int ix  = rem % IROW;
                int gy = by + iy - 1;
                int gx = bx + ix - 1;
                float v = 0.0f;
                if (gy >= 0 && gy < H && gx >= 0 && gx < W)
                    v = in[(((size_t)n * CIN + c0 + c) * H + gy) * W + gx];
                insm[c][iy][ix] = v;
            }
        }
        __syncthreads();

        #pragma unroll 1
        for (int c = 0; c < CHUNK; ++c) {
            #pragma unroll
            for (int ky = 0; ky < 3; ++ky) {
                const float* rp = &insm[c][row + ky][col];
                unsigned long long d[10];
                #pragma unroll
                for (int i = 0; i < 10; ++i) d[i] = dup2(rp[i]);
                #pragma unroll
                for (int kx = 0; kx < 3; ++kx) {
                    const float* wp = &wsm[c][ky * 3 + kx][woff];
                    unsigned long long w2[4];
                    #pragma unroll
                    for (int j = 0; j < 4; ++j)
                        w2[j] = *reinterpret_cast<const unsigned long long*>(wp + 2 * j);
                    #pragma unroll
                    for (int op = 0; op < 4; ++op)
                        #pragma unroll
                        for (int p = 0; p < 8; ++p)
                            acc[op][p] = fma2(w2[op], d[kx + p], acc[op][p]);
                }
            }
        }
        __syncthreads();
    }

    const int gy = by + row;
    const int gx = bx + col;
    #pragma unroll
    for (int op = 0; op < 4; ++op) {
        const int oc0 = oc_base + ocg * 8 + 2 * op;
        const float b0 = bias[oc0];
        const float b1 = bias[oc0 + 1];
        float lo[8], hi[8];
        #pragma unroll
        for (int p = 0; p < 8; ++p) {
            float2 u = unpack2(acc[op][p]);
            lo[p] = fmaxf(u.x + b0, 0.0f);
            hi[p] = fmaxf(u.y + b1, 0.0f);
            if (ROUND) {
                lo[p] = __uint_as_float(f32_to_tf32(lo[p]));
                hi[p] = __uint_as_float(f32_to_tf32(hi[p]));
            }
        }
        float* dst0 = out + (((size_t)n * COUT + oc0) * H + gy) * W + gx;
        float* dst1 = dst0 + (size_t)H * W;
        *reinterpret_cast<float4*>(dst0)     = make_float4(lo[0], lo[1], lo[2], lo[3]);
        *reinterpret_cast<float4*>(dst0 + 4) = make_float4(lo[4], lo[5], lo[6], lo[7]);
        *reinterpret_cast<float4*>(dst1)     = make_float4(hi[0], hi[1], hi[2], hi[3]);
        *reinterpret_cast<float4*>(dst1 + 4) = make_float4(hi[4], hi[5], hi[6], hi[7]);
    }
}

// ============================ launchers ====================================
static constexpr int SMEM_MMA = 2 * (4 * 202 * 4) * 4;   // 25856 B

template <int CIN, int COUT, bool ROUND, bool POOL>
static inline void launch_tconv(const float* in, const float* wT, const float* b,
                                float* out, int H, int W, int N)
{
    cudaFuncSetAttribute(conv3x3_mma<CIN, COUT, ROUND, POOL>,
                         cudaFuncAttributeMaxDynamicSharedMemorySize, SMEM_MMA);
    dim3 grid((W / 16) * (H / 8), N, COUT / 64);
    conv3x3_mma<CIN, COUT, ROUND, POOL><<<grid, 128, SMEM_MMA>>>(in, wT, b, out, H, W);
}

extern "C" void kernel_launch(void* const* d_in, const int* in_sizes, int n_in,
                              void* d_out, int out_size)
{
    (void)in_sizes; (void)n_in; (void)out_size;

    const float* x = (const float*)d_in[0];          // (2,3,384,384)
    const float* w[11];
    const float* b[11];
    for (int k = 1; k <= 10; ++k) {
        w[k] = (const float*)d_in[2 + 2 * (k - 1)];
        b[k] = (const float*)d_in[3 + 2 * (k - 1)];
    }

    float* A;
    float* Bb;
    float* Wt;
    cudaGetSymbolAddress((void**)&A,  g_bufA);
    cudaGetSymbolAddress((void**)&Bb, g_bufB);
    cudaGetSymbolAddress((void**)&Wt, g_bufW);
    float* O = (float*)d_out;
    const int N = 2;

    // ---- fused fragment-major transform of conv2..conv10 weights
    static const int CO[9] = {64, 128, 128, 256, 256, 256, 512, 512, 512};
    static const int CI[9] = {64,  64, 128, 128, 256, 256, 256, 512, 512};
    WXform p;
    long off = 0;
    for (int l = 0; l < 9; ++l) {
        p.src[l] = w[l + 2];
        p.cout[l] = CO[l];
        p.cin[l]  = CI[l];
        p.start[l] = off;
        off += (long)CO[l] * CI[l] * 9;
    }
    p.start[9] = off;
    {
        long blocks = (off + 255) / 256;
        transform_all<<<(unsigned)blocks, 256>>>(p, Wt);
    }

    // Stage 1 @ 384x384 — conv1 FFMA, conv2 tensor + fused pool -> 192^2
    {
        dim3 grid((384 / 32) * (384 / 8), N, 1);
        conv3x3_ffma<3, 64, 3, 8, 32, true><<<grid, 256>>>(x, w[1], b[1], A, 384, 384);
    }
    launch_tconv<64, 64, true, true>(A, Wt + p.start[0], b[2], Bb, 384, 384, N);

    // Stage 2 @ 192x192 — conv3, conv4 + fused pool -> 96^2
    launch_tconv<64, 128, true, false>(Bb, Wt + p.start[1], b[3], A, 192, 192, N);
    launch_tconv<128, 128, true, true>(A,  Wt + p.start[2], b[4], Bb, 192, 192, N);

    // Stage 3 @ 96x96 — conv5, conv6, conv7 + fused pool -> 48^2
    launch_tconv<128, 256, true, false>(Bb, Wt + p.start[3], b[5], A,  96, 96, N);
    launch_tconv<256, 256, true, false>(A,  Wt + p.start[4], b[6], Bb, 96, 96, N);
    launch_tconv<256, 256, true, true>(Bb,  Wt + p.start[5], b[7], A,  96, 96, N);

    // Stage 4 @ 48x48
    launch_tconv<256, 512, true, false>(A,  Wt + p.start[6], b[8],  Bb, 48, 48, N);
    launch_tconv<512, 512, true, false>(Bb, Wt + p.start[7], b[9],  A,  48, 48, N);
    launch_tconv<512, 512, false, false>(A, Wt + p.start[8], b[10], O,  48, 48, N);
}

// round 15
// speedup vs baseline: 1.9060x; 1.9060x over previous
#include <cuda_runtime.h>
#include <cuda_bf16.h>
#include <cstdint>

// ---------------------------------------------------------------------------
// APD2Net: graph_conv == 3x3 SAME conv (weights (O,C,9), k=ky*3+kx),
// graph_pool == 2x2 maxpool. NCHW fp32 end-to-end.
//
// R15 = R13 dataflow (A fragment-major smem, k-interleaved X, fused pools)
// with 256-thread blocks / 8 warps (2m x 4n) and 32 acc regs per thread:
// 16 warps/SM instead of 8 -> feed the tensor pipe.
// ---------------------------------------------------------------------------

__device__ float g_bufA[2u * 64u * 384u * 384u];
__device__ float g_bufB[2u * 64u * 384u * 384u];
__device__ float g_bufW[7630848u];               // all transformed weights

__device__ __forceinline__ uint32_t f32_to_tf32(float v) {
    uint32_t t;
    asm("cvt.rna.tf32.f32 %0, %1;" : "=r"(t) : "f"(v));
    return t;
}
__device__ __forceinline__ void cp_async4(void* smem_dst, const void* gptr, int src_bytes) {
    unsigned sa = (unsigned)__cvta_generic_to_shared(smem_dst);
    asm volatile("cp.async.ca.shared.global [%0], [%1], 4, %2;\n"
                 :: "r"(sa), "l"(gptr), "r"(src_bytes));
}
__device__ __forceinline__ void cp_async16(void* smem_dst, const void* gptr) {
    unsigned sa = (unsigned)__cvta_generic_to_shared(smem_dst);
    asm volatile("cp.async.cg.shared.global [%0], [%1], 16;\n"
                 :: "r"(sa), "l"(gptr));
}
__device__ __forceinline__ void cp_commit() { asm volatile("cp.async.commit_group;"); }
__device__ __forceinline__ void cp_wait1()  { asm volatile("cp.async.wait_group 1;"); }
__device__ __forceinline__ void cp_wait0()  { asm volatile("cp.async.wait_group 0;"); }

// ============================ fused weight transform ========================
// Per layer: w (COUT,CIN,9) -> fragment-major (z)(tap)(k8g)(q)(lane)(reg)
struct WXform {
    const float* src[9];
    long start[10];
    int cout[9], cin[9];
};

__global__ void transform_all(WXform p, float* __restrict__ dstbase)
{
    long gid0 = (long)blockIdx.x * blockDim.x + threadIdx.x;
    if (gid0 >= p.start[9]) return;
    int l = 0;
    #pragma unroll
    for (int i = 1; i < 9; ++i) if (gid0 >= p.start[i]) l = i;
    long i = gid0 - p.start[l];
    const int CIN = p.cin[l];
    const int K8 = CIN / 8;

    int reg  = (int)(i & 3);
    int lane = (int)((i >> 2) & 31);
    int q    = (int)((i >> 7) & 3);
    long r   = i >> 9;                 // (z*9 + t)*K8 + k8g
    int k8g  = (int)(r % K8);
    long zt  = r / K8;
    int t    = (int)(zt % 9);
    int z    = (int)(zt / 9);

    int tig = lane & 3, gidl = lane >> 2;
    int mhalf = reg & 1, khalf = reg >> 1;
    int oc = z * 64 + q * 16 + mhalf * 8 + gidl;
    int c  = k8g * 8 + khalf * 4 + tig;
    float v = p.src[l][((size_t)oc * CIN + c) * 9 + t];
    dstbase[p.start[l] + i] = __uint_as_float(f32_to_tf32(v));
}

// ============================ tensor conv ==================================
// Block 256 thr = 8 warps: warp_m = wid&1 (2 x 32oc), warp_n = wid>>1 (4 x 32px)
// CTA tile: 64 oc x 128 px (8y x 16x). KC=16 double-buffered.
// As[2][9][1024] fragment-major. Xs: k-interleaved float4 planes (pitch 202).
template <int CIN, int COUT, bool ROUND, bool POOL>
__global__ void __launch_bounds__(256, 2)
conv3x3_mma(const float* __restrict__ in,
            const float* __restrict__ wT,
            const float* __restrict__ bias,
            float* __restrict__ out, int H, int W)
{
    constexpr int KC = 16;
    static_assert(CIN % KC == 0, "");
    constexpr int NCH = CIN / KC;
    constexpr int K8 = CIN / 8;
    constexpr int ASTG = 9 * 1024;             // floats per A stage
    constexpr int XPL = 202;                   // plane pitch in 16B units
    constexpr int XSTG = 4 * XPL * 4;          // floats per X stage (3232)

    extern __shared__ float sm[];
    float* As = sm;                            // [2][ASTG]
    float* Xs = sm + 2 * ASTG;                 // [2][XSTG]

    const int tid  = threadIdx.x;
    const int lane = tid & 31;
    const int wid  = tid >> 5;
    const int gid  = lane >> 2;
    const int tig  = lane & 3;
    const int warp_m = wid & 1;
    const int warp_n = wid >> 1;               // 0..3

    const int tiles_x = W / 16;
    const int bx = (blockIdx.x % tiles_x) * 16;
    const int by = (blockIdx.x / tiles_x) * 8;
    const int n_img = blockIdx.y;
    const int zsl = blockIdx.z;
    const int oc_base = zsl * 64;

    float acc[2][4][4];
    #pragma unroll
    for (int mt = 0; mt < 2; ++mt)
        #pragma unroll
        for (int nt = 0; nt < 4; ++nt)
            #pragma unroll
            for (int r = 0; r < 4; ++r) acc[mt][nt][r] = 0.0f;

    int b_y0[4], b_x[4];
    #pragma unroll
    for (int nt = 0; nt < 4; ++nt) {
        int n_base = warp_n * 32 + nt * 8;
        b_y0[nt] = n_base >> 4;
        b_x[nt]  = (n_base & 15) + gid;
    }

    const float* wz = wT + (size_t)zsl * 9 * K8 * 512;

    auto load_chunk = [&](int s, int ch) {
        // A: 9 taps x 1024 floats, linear per tap (float4 cp.async)
        {
            float* dst = As + s * ASTG;
            #pragma unroll
            for (int it = 0; it < 9; ++it) {       // 9*256 float4 / 256 thr
                int idx = it * 256 + tid;
                int tap = idx >> 8;
                int f4  = idx & 255;
                cp_async16(dst + tap * 1024 + f4 * 4,
                           wz + ((size_t)tap * K8 + 2 * ch) * 512 + f4 * 4);
            }
        }
        // X: 16 cin x 10 y x 18 x -> k-interleaved float4 planes
        {
            const int c0 = ch * KC;
            constexpr int TOT = KC * 10 * 18;      // 2880
            float* dst = Xs + s * XSTG;
            #pragma unroll
            for (int it = 0; it < (TOT + 255) / 256; ++it) {
                int idx = it * 256 + tid;
                if (idx < TOT) {
                    int c  = idx / 180;
                    int r  = idx % 180;
                    int yy = r / 18;
                    int xx = r % 18;
                    int ctig = c & 3;
                    int j    = c >> 2;
                    int gy = by + yy - 1;
                    int gx = bx + xx - 1;
                    bool ok = (gy >= 0 && gy < H && gx >= 0 && gx < W);
                    const float* src = ok
                        ? in + (((size_t)n_img * CIN + c0 + c) * H + gy) * W + gx
                        : in;
                    cp_async4(dst + (ctig * XPL + yy * 20 + xx) * 4 + j,
                              src, ok ? 4 : 0);
                }
            }
        }
        cp_commit();
    };

    load_chunk(0, 0);

    #pragma unroll 1
    for (int ch = 0; ch < NCH; ++ch) {
        const int s = ch & 1;
        if (ch + 1 < NCH) { load_chunk(s ^ 1, ch + 1); cp_wait1(); }
        else              { cp_wait0(); }
        __syncthreads();

        const float* ab0 = As + s * ASTG;
        const float4* xb = reinterpret_cast<const float4*>(Xs + s * XSTG)
                         + tig * XPL;

        #pragma unroll 1
        for (int tap = 0; tap < 9; ++tap) {
            const int ky = tap / 3, kx = tap % 3;
            const float* ab = ab0 + tap * 1024;
            uint32_t a[2][2][4];
            #pragma unroll
            for (int ks = 0; ks < 2; ++ks)
                #pragma unroll
                for (int mt = 0; mt < 2; ++mt) {
                    int q = warp_m * 2 + mt;
                    const float4 af = *reinterpret_cast<const float4*>(
                        ab + ks * 512 + q * 128 + lane * 4);
                    a[ks][mt][0] = __float_as_uint(af.x);
                    a[ks][mt][1] = __float_as_uint(af.y);
                    a[ks][mt][2] = __float_as_uint(af.z);
                    a[ks][mt][3] = __float_as_uint(af.w);
                }
            #pragma unroll
            for (int nt = 0; nt < 4; ++nt) {
                const float4 bf = xb[(b_y0[nt] + ky) * 20 + b_x[nt] + kx];
                uint32_t b00 = __float_as_uint(bf.x);
                uint32_t b01 = __float_as_uint(bf.y);
                uint32_t b10 = __float_as_uint(bf.z);
                uint32_t b11 = __float_as_uint(bf.w);
                #pragma unroll
                for (int mt = 0; mt < 2; ++mt) {
                    float* d = acc[mt][nt];
                    asm volatile(
                        "mma.sync.aligned.m16n8k8.row.col.f32.tf32.tf32.f32 "
                        "{%0,%1,%2,%3}, {%4,%5,%6,%7}, {%8,%9}, {%0,%1,%2,%3};"
                        : "+f"(d[0]), "+f"(d[1]), "+f"(d[2]), "+f"(d[3])
                        : "r"(a[0][mt][0]), "r"(a[0][mt][1]),
                          "r"(a[0][mt][2]), "r"(a[0][mt][3]),
                          "r"(b00), "r"(b01));
                    asm volatile(
                        "mma.sync.aligned.m16n8k8.row.col.f32.tf32.tf32.f32 "
                        "{%0,%1,%2,%3}, {%4,%5,%6,%7}, {%8,%9}, {%0,%1,%2,%3};"
                        : "+f"(d[0]), "+f"(d[1]), "+f"(d[2]), "+f"(d[3])
                        : "r"(a[1][mt][0]), "r"(a[1][mt][1]),
                          "r"(a[1][mt][2]), "r"(a[1][mt][3]),
                          "r"(b10), "r"(b11));
                }
            }
        }
        __syncthreads();
    }

    // ---- epilogue
    if (POOL) {
        // fused 2x2 maxpool: y0 = warp_n*2 + (nt>>1); pairs (nt, nt+2), nt in {0,1}
        const int Ho = H >> 1, Wo = W >> 1;
        #pragma unroll
        for (int mt = 0; mt < 2; ++mt) {
            int oc0 = oc_base + (warp_m * 2 + mt) * 16 + gid;
            float bv0 = bias[oc0];
            float bv1 = bias[oc0 + 8];
            #pragma unroll
            for (int g = 0; g < 2; ++g) {
                int nt  = g;
                int ntb = g + 2;
                float p0 = fmaxf(fmaxf(acc[mt][nt][0],  acc[mt][nt][1]),
                                 fmaxf(acc[mt][ntb][0], acc[mt][ntb][1]));
                float p1 = fmaxf(fmaxf(acc[mt][nt][2],  acc[mt][nt][3]),
                                 fmaxf(acc[mt][ntb][2], acc[mt][ntb][3]));
                p0 = fmaxf(p0 + bv0, 0.0f);
                p1 = fmaxf(p1 + bv1, 0.0f);
                if (ROUND) {
                    p0 = __uint_as_float(f32_to_tf32(p0));
                    p1 = __uint_as_float(f32_to_tf32(p1));
                }
                int px = warp_n * 32 + nt * 8 + tig * 2;
                int oy = (by + (px >> 4)) >> 1;
                int ox = (bx + (px & 15)) >> 1;
                out[(((size_t)n_img * COUT + oc0) * Ho + oy) * Wo + ox] = p0;
                out[(((size_t)n_img * COUT + oc0 + 8) * Ho + oy) * Wo + ox] = p1;
            }
        }
    } else {
        #pragma unroll
        for (int mt = 0; mt < 2; ++mt) {
            int oc0 = oc_base + (warp_m * 2 + mt) * 16 + gid;
            float bv0 = bias[oc0];
            float bv1 = bias[oc0 + 8];
            #pragma unroll
            for (int nt = 0; nt < 4; ++nt) {
                int px = warp_n * 32 + nt * 8 + tig * 2;
                int gy = by + (px >> 4);
                int gx = bx + (px & 15);
                float v00 = fmaxf(acc[mt][nt][0] + bv0, 0.0f);
                float v01 = fmaxf(acc[mt][nt][1] + bv0, 0.0f);
                float v10 = fmaxf(acc[mt][nt][2] + bv1, 0.0f);
                float v11 = fmaxf(acc[mt][nt][3] + bv1, 0.0f);
                if (ROUND) {
                    v00 = __uint_as_float(f32_to_tf32(v00));
                    v01 = __uint_as_float(f32_to_tf32(v01));
                    v10 = __uint_as_float(f32_to_tf32(v10));
                    v11 = __uint_as_float(f32_to_tf32(v11));
                }
                float* d0 = out + (((size_t)n_img * COUT + oc0) * H + gy) * W + gx;
                float* d1 = d0 + (size_t)8 * H * W;
                *reinterpret_cast<float2*>(d0) = make_float2(v00, v01);
                *reinterpret_cast<float2*>(d1) = make_float2(v10, v11);
            }
        }
    }
}

// ============================ FFMA2 conv (conv1 only) ======================
__device__ __forceinline__ unsigned long long fma2(unsigned long long a,
                                                   unsigned long long b,
                                                   unsigned long long c) {
    unsigned long long d;
    asm("fma.rn.f32x2 %0, %1, %2, %3;" : "=l"(d) : "l"(a), "l"(b), "l"(c));
    return d;
}
__device__ __forceinline__ unsigned long long dup2(float v) {
    unsigned long long d;
    asm("mov.b64 %0, {%1, %1};" : "=l"(d) : "f"(v));
    return d;
}
__device__ __forceinline__ float2 unpack2(unsigned long long v) {
    float2 r;
    asm("mov.b64 {%0, %1}, %2;" : "=f"(r.x), "=f"(r.y) : "l"(v));
    return r;
}
__device__ __host__ __forceinline__ int woff_of(int ocg) {
    return ocg * 8 + (ocg >> 2) * 2;
}

template <int CIN, int COUT, int CHUNK, int TH, int TW, bool ROUND>
__global__ void __launch_bounds__(256, 2)
conv3x3_ffma(const float* __restrict__ in,
             const float* __restrict__ wgt,
             const float* __restrict__ bias,
             float* __restrict__ out, int H, int W)
{
    constexpr int OCB = 64;
    constexpr int WROW = 68;
    constexpr int IROW = TW + 2;
    constexpr int CG = TW / 8;

    __shared__ __align__(16) float wsm[CHUNK][9][WROW];
    __shared__ float insm[CHUNK][TH + 2][IROW];

    const int tiles_x = W / TW;
    const int bx = (blockIdx.x % tiles_x) * TW;
    const int by = (blockIdx.x / tiles_x) * TH;
    const int n  = blockIdx.y;
    const int oc_base = blockIdx.z * OCB;

    const int tid = threadIdx.x;
    const int ocg = tid & 7;
    const int pg  = tid >> 3;
    const int row = pg / CG;
    const int col = (pg % CG) * 8;
    const int woff = woff_of(ocg);

    unsigned long long acc[4][8];
    #pragma unroll
    for (int op = 0; op < 4; ++op)
        #pragma unroll
        for (int p = 0; p < 8; ++p) acc[op][p] = 0ull;

    #pragma unroll 1
    for (int c0 = 0; c0 < CIN; c0 += CHUNK) {
        {
            const float* wg = wgt + (size_t)oc_base * CIN * 9 + (size_t)c0 * 9;
            constexpr int PER_OC = CHUNK * 9;
            constexpr int TOT = OCB * PER_OC;
            for (int idx = tid; idx < TOT; idx += 256) {
                int oc = idx / PER_OC;
                int r  = idx % PER_OC;
                float v = wg[(size_t)oc * CIN * 9 + r];
                wsm[r / 9][r % 9][woff_of(oc >> 3) + (oc & 7)] = v;
            }
        }
        {
            constexpr int TILE2D = (TH + 2) * IROW;
            constexpr int TOT = CHUNK * TILE2D;
            for (int idx = tid; idx < TOT; idx += 256) {
                int c   = idx / TILE2D;
                int rem = idx % TILE2D;
                int iy  = rem / IROW;
                int ix  = rem % IROW;
                int gy = by + iy - 1;
                int gx = bx + ix - 1;
                float v = 0.0f;
                if (gy >= 0 && gy < H && gx >= 0 && gx < W)
                    v = in[(((size_t)n * CIN + c0 + c) * H + gy) * W + gx];
                insm[c][iy][ix] = v;
            }
        }
        __syncthreads();

        #pragma unroll 1
        for (int c = 0; c < CHUNK; ++c) {
            #pragma unroll
            for (int ky = 0; ky < 3; ++ky) {
                const float* rp = &insm[c][row + ky][col];
                unsigned long long d[10];
                #pragma unroll
                for (int i = 0; i < 10; ++i) d[i] = dup2(rp[i]);
                #pragma unroll
                for (int kx = 0; kx < 3; ++kx) {
                    const float* wp = &wsm[c][ky * 3 + kx][woff];
                    unsigned long long w2[4];
                    #pragma unroll
                    for (int j = 0; j < 4; ++j)
                        w2[j] = *reinterpret_cast<const unsigned long long*>(wp + 2 * j);
                    #pragma unroll
                    for (int op = 0; op < 4; ++op)
                        #pragma unroll
                        for (int p = 0; p < 8; ++p)
                            acc[op][p] = fma2(w2[op], d[kx + p], acc[op][p]);
                }
            }
        }
        __syncthreads();
    }

    const int gy = by + row;
    const int gx = bx + col;
    #pragma unroll
    for (int op = 0; op < 4; ++op) {
        const int oc0 = oc_base + ocg * 8 + 2 * op;
        const float b0 = bias[oc0];
        const float b1 = bias[oc0 + 1];
        float lo[8], hi[8];
        #pragma unroll
        for (int p = 0; p < 8; ++p) {
            float2 u = unpack2(acc[op][p]);
            lo[p] = fmaxf(u.x + b0, 0.0f);
            hi[p] = fmaxf(u.y + b1, 0.0f);
            if (ROUND) {
                lo[p] = __uint_as_float(f32_to_tf32(lo[p]));
                hi[p] = __uint_as_float(f32_to_tf32(hi[p]));
            }
        }
        float* dst0 = out + (((size_t)n * COUT + oc0) * H + gy) * W + gx;
        float* dst1 = dst0 + (size_t)H * W;
        *reinterpret_cast<float4*>(dst0)     = make_float4(lo[0], lo[1], lo[2], lo[3]);
        *reinterpret_cast<float4*>(dst0 + 4) = make_float4(lo[4], lo[5], lo[6], lo[7]);
        *reinterpret_cast<float4*>(dst1)     = make_float4(hi[0], hi[1], hi[2], hi[3]);
        *reinterpret_cast<float4*>(dst1 + 4) = make_float4(hi[4], hi[5], hi[6], hi[7]);
    }
}

// ============================ launchers ====================================
static constexpr int SMEM_MMA = (2 * 9 * 1024 + 2 * (4 * 202 * 4)) * 4; // 99584 B

template <int CIN, int COUT, bool ROUND, bool POOL>
static inline void launch_tconv(const float* in, const float* wT, const float* b,
                                float* out, int H, int W, int N)
{
    cudaFuncSetAttribute(conv3x3_mma<CIN, COUT, ROUND, POOL>,
                         cudaFuncAttributeMaxDynamicSharedMemorySize, SMEM_MMA);
    dim3 grid((W / 16) * (H / 8), N, COUT / 64);
    conv3x3_mma<CIN, COUT, ROUND, POOL><<<grid, 256, SMEM_MMA>>>(in, wT, b, out, H, W);
}

extern "C" void kernel_launch(void* const* d_in, const int* in_sizes, int n_in,
                              void* d_out, int out_size)
{
    (void)in_sizes; (void)n_in; (void)out_size;

    const float* x = (const float*)d_in[0];          // (2,3,384,384)
    const float* w[11];
    const float* b[11];
    for (int k = 1; k <= 10; ++k) {
        w[k] = (const float*)d_in[2 + 2 * (k - 1)];
        b[k] = (const float*)d_in[3 + 2 * (k - 1)];
    }

    float* A;
    float* Bb;
    float* Wt;
    cudaGetSymbolAddress((void**)&A,  g_bufA);
    cudaGetSymbolAddress((void**)&Bb, g_bufB);
    cudaGetSymbolAddress((void**)&Wt, g_bufW);
    float* O = (float*)d_out;
    const int N = 2;

    // ---- fused fragment-major transform of conv2..conv10 weights
    static const int CO[9] = {64, 128, 128, 256, 256, 256, 512, 512, 512};
    static const int CI[9] = {64,  64, 128, 128, 256, 256, 256, 512, 512};
    WXform p;
    long off = 0;
    for (int l = 0; l < 9; ++l) {
        p.src[l] = w[l + 2];
        p.cout[l] = CO[l];
        p.cin[l]  = CI[l];
        p.start[l] = off;
        off += (long)CO[l] * CI[l] * 9;
    }
    p.start[9] = off;
    {
        long blocks = (off + 255) / 256;
        transform_all<<<(unsigned)blocks, 256>>>(p, Wt);
    }

    // Stage 1 @ 384x384 — conv1 FFMA, conv2 tensor + fused pool -> 192^2
    {
        dim3 grid((384 / 32) * (384 / 8), N, 1);
        conv3x3_ffma<3, 64, 3, 8, 32, true><<<grid, 256>>>(x, w[1], b[1], A, 384, 384);
    }
    launch_tconv<64, 64, true, true>(A, Wt + p.start[0], b[2], Bb, 384, 384, N);

    // Stage 2 @ 192x192 — conv3, conv4 + fused pool -> 96^2
    launch_tconv<64, 128, true, false>(Bb, Wt + p.start[1], b[3], A, 192, 192, N);
    launch_tconv<128, 128, true, true>(A,  Wt + p.start[2], b[4], Bb, 192, 192, N);

    // Stage 3 @ 96x96 — conv5, conv6, conv7 + fused pool -> 48^2
    launch_tconv<128, 256, true, false>(Bb, Wt + p.start[3], b[5], A,  96, 96, N);
    launch_tconv<256, 256, true, false>(A,  Wt + p.start[4], b[6], Bb, 96, 96, N);
    launch_tconv<256, 256, true, true>(Bb,  Wt + p.start[5], b[7], A,  96, 96, N);

    // Stage 4 @ 48x48
    launch_tconv<256, 512, true, false>(A,  Wt + p.start[6], b[8],  Bb, 48, 48, N);
    launch_tconv<512, 512, true, false>(Bb, Wt + p.start[7], b[9],  A,  48, 48, N);
    launch_tconv<512, 512, false, false>(A, Wt + p.start[8], b[10], O,  48, 48, N);
}

// round 17
// speedup vs baseline: 2.9087x; 1.5261x over previous
#include <cuda_runtime.h>
#include <cuda_fp16.h>
#include <cstdint>

// ---------------------------------------------------------------------------
// APD2Net: graph_conv == 3x3 SAME conv (weights (O,C,9), k=ky*3+kx),
// graph_pool == 2x2 maxpool. Output fp32 NCHW.
//
// R17 = R16 (fp16 m16n8k16 tensor path) with the batch-offset bug fixed in
// the X staging (channel-pair index now includes n_img*CIN/2).
//  - activations fp16 CHANNEL-PAIR-INTERLEAVED:
//        a[(((n*C+c)>>1)*H*W + y*W + x)*2 + (c&1)]
//  - weights fp16 fragment-major (one LDS.128 = full A fragment).
//  - per tap per warp: 2 LDS.128 + 4 LDS.64 feed 8 k16-MMAs.
//  - 2x2 maxpool fused into conv2/conv4/conv7 epilogues. conv1 stays FFMA2.
// ---------------------------------------------------------------------------

__device__ float g_bufA[2u * 64u * 384u * 384u];   // used as __half (cpair)
__device__ float g_bufB[2u * 64u * 384u * 384u];
__device__ float g_bufW[7630848u];                 // used as __half fragment-major

__device__ __forceinline__ void cp_async4(void* smem_dst, const void* gptr, int src_bytes) {
    unsigned sa = (unsigned)__cvta_generic_to_shared(smem_dst);
    asm volatile("cp.async.ca.shared.global [%0], [%1], 4, %2;\n"
                 :: "r"(sa), "l"(gptr), "r"(src_bytes));
}
__device__ __forceinline__ void cp_async16(void* smem_dst, const void* gptr) {
    unsigned sa = (unsigned)__cvta_generic_to_shared(smem_dst);
    asm volatile("cp.async.cg.shared.global [%0], [%1], 16;\n"
                 :: "r"(sa), "l"(gptr));
}
__device__ __forceinline__ void cp_commit() { asm volatile("cp.async.commit_group;"); }
__device__ __forceinline__ void cp_wait1()  { asm volatile("cp.async.wait_group 1;"); }
__device__ __forceinline__ void cp_wait0()  { asm volatile("cp.async.wait_group 0;"); }

// ============================ fused weight transform ========================
// Per layer: w (COUT,CIN,9) fp32 -> fp16 fragment-major for m16n8k16:
//   half index i: h=i&1, reg=(i>>1)&3, lane=(i>>3)&31, q=(i>>8)&3,
//   rest=i>>10: k16g=rest%K16, t=(rest/K16)%9, z=rest/(9*K16)
//   oc = z*64 + q*16 + (reg&1)*8 + (lane>>2)
//   k  = k16g*16 + (reg>>1)*8 + (lane&3)*2 + h
struct WXform {
    const float* src[9];
    long start[10];          // half-index offsets
    int cout[9], cin[9];
};

__global__ void transform_all(WXform p, __half* __restrict__ dstbase)
{
    long gid0 = (long)blockIdx.x * blockDim.x + threadIdx.x;
    if (gid0 >= p.start[9]) return;
    int l = 0;
    #pragma unroll
    for (int i = 1; i < 9; ++i) if (gid0 >= p.start[i]) l = i;
    long i = gid0 - p.start[l];
    const int CIN = p.cin[l];
    const int K16 = CIN / 16;

    int h    = (int)(i & 1);
    int reg  = (int)((i >> 1) & 3);
    int lane = (int)((i >> 3) & 31);
    int q    = (int)((i >> 8) & 3);
    long rest = i >> 10;
    int k16g = (int)(rest % K16);
    long zt  = rest / K16;
    int t    = (int)(zt % 9);
    int z    = (int)(zt / 9);

    int tig = lane & 3, gidl = lane >> 2;
    int oc = z * 64 + q * 16 + (reg & 1) * 8 + gidl;
    int k  = k16g * 16 + (reg >> 1) * 8 + tig * 2 + h;
    float v = p.src[l][((size_t)oc * CIN + k) * 9 + t];
    dstbase[p.start[l] + i] = __float2half_rn(v);
}

// ============================ tensor conv (fp16) ===========================
// Block 256 thr = 8 warps: warp_m = wid&1 (2 x 32oc), warp_n = wid>>1 (4 x 32px)
// CTA tile: 64 oc x 128 px (8y x 16x). KC=16 double-buffered.
// As[2][9][128 float4] fragment-major. Xs: 4 planes, pitch 204 8B-words,
//   word(t, yy, xx) = { half2 pair t , half2 pair t+4 }  (pairs of KC=16).
template <int CIN, int COUT, bool ROUND, bool POOL>
__global__ void __launch_bounds__(256, 2)
conv3x3_mma(const __half* __restrict__ in,     // cpair layout
            const __half* __restrict__ wT,     // fragment-major fp16
            const float* __restrict__ bias,
            void* __restrict__ out_raw, int H, int W)
{
    constexpr int KC = 16;
    static_assert(CIN % KC == 0, "");
    constexpr int NCH = CIN / KC;
    constexpr int K16 = CIN / 16;
    constexpr int ASTG4 = 9 * 128;             // float4 per A stage (1152)
    constexpr int XPL = 204;                   // 8B words per plane
    constexpr int XSTGf = 4 * XPL * 2;         // floats per X stage (1632)

    extern __shared__ float sm[];
    float4* As = reinterpret_cast<float4*>(sm);          // [2][ASTG4]
    float*  Xs = sm + 2 * ASTG4 * 4;                     // [2][XSTGf]

    const int tid  = threadIdx.x;
    const int lane = tid & 31;
    const int wid  = tid >> 5;
    const int gid  = lane >> 2;
    const int tig  = lane & 3;
    const int warp_m = wid & 1;
    const int warp_n = wid >> 1;               // 0..3

    const int tiles_x = W / 16;
    const int bx = (blockIdx.x % tiles_x) * 16;
    const int by = (blockIdx.x / tiles_x) * 8;
    const int n_img = blockIdx.y;
    const int zsl = blockIdx.z;
    const int oc_base = zsl * 64;
    const size_t HW = (size_t)H * W;

    float acc[2][4][4];
    #pragma unroll
    for (int mt = 0; mt < 2; ++mt)
        #pragma unroll
        for (int nt = 0; nt < 4; ++nt)
            #pragma unroll
            for (int r = 0; r < 4; ++r) acc[mt][nt][r] = 0.0f;

    int b_y0[4], b_x[4];
    #pragma unroll
    for (int nt = 0; nt < 4; ++nt) {
        int n_base = warp_n * 32 + nt * 8;
        b_y0[nt] = n_base >> 4;
        b_x[nt]  = (n_base & 15) + gid;
    }

    // layer z-slice base in float4 units: 9*K16*128 float4 per z
    const float4* wz4 = reinterpret_cast<const float4*>(wT)
                      + (size_t)zsl * 9 * K16 * 128;

    // batch base in channel-pair units
    const size_t pair_base = (size_t)n_img * (CIN / 2);

    auto load_chunk = [&](int s, int ch) {
        // A: 9 taps x 128 float4 per chunk, linear copy
        {
            float4* dst = As + s * ASTG4;
            #pragma unroll
            for (int it = 0; it < 5; ++it) {
                int idx = it * 256 + tid;
                if (idx < ASTG4) {
                    int tap = idx >> 7;
                    int r   = idx & 127;
                    cp_async16(dst + tap * 128 + r,
                               wz4 + ((size_t)tap * K16 + ch) * 128 + r);
                }
            }
        }
        // X: 8 channel-pairs x 10y x 18x half2 -> interleaved planes
        {
            const int p0 = ch * 8;                 // pair base within image
            constexpr int TOT = 8 * 10 * 18;       // 1440
            float* dst = Xs + s * XSTGf;
            #pragma unroll
            for (int it = 0; it < (TOT + 255) / 256; ++it) {
                int idx = it * 256 + tid;
                if (idx < TOT) {
                    int p  = idx / 180;
                    int r  = idx % 180;
                    int yy = r / 18;
                    int xx = r % 18;
                    int t  = p & 3;
                    int j  = p >> 2;
                    int gy = by + yy - 1;
                    int gx = bx + xx - 1;
                    bool ok = (gy >= 0 && gy < H && gx >= 0 && gx < W);
                    const __half* src = ok
                        ? in + ((pair_base + p0 + p) * HW + (size_t)gy * W + gx) * 2
                        : in;
                    cp_async4(dst + (t * XPL + yy * 20 + xx) * 2 + j,
                              src, ok ? 4 : 0);
                }
            }
        }
        cp_commit();
    };

    load_chunk(0, 0);

    #pragma unroll 1
    for (int ch = 0; ch < NCH; ++ch) {
        const int s = ch & 1;
        if (ch + 1 < NCH) { load_chunk(s ^ 1, ch + 1); cp_wait1(); }
        else              { cp_wait0(); }
        __syncthreads();

        const float4* ab0 = As + s * ASTG4;
        const float2* xb  = reinterpret_cast<const float2*>(Xs + s * XSTGf)
                          + tig * XPL;

        #pragma unroll 1
        for (int tap = 0; tap < 9; ++tap) {
            const int ky = tap / 3, kx = tap % 3;
            const float4* ab = ab0 + tap * 128;
            uint32_t a[2][4];
            #pragma unroll
            for (int mt = 0; mt < 2; ++mt) {
                int q = warp_m * 2 + mt;
                float4 af = ab[q * 32 + lane];
                a[mt][0] = __float_as_uint(af.x);
                a[mt][1] = __float_as_uint(af.y);
                a[mt][2] = __float_as_uint(af.z);
                a[mt][3] = __float_as_uint(af.w);
            }
            #pragma unroll
            for (int nt = 0; nt < 4; ++nt) {
                float2 bf = xb[(b_y0[nt] + ky) * 20 + b_x[nt] + kx];
                uint32_t b0 = __float_as_uint(bf.x);
                uint32_t b1 = __float_as_uint(bf.y);
                #pragma unroll
                for (int mt = 0; mt < 2; ++mt) {
                    float* d = acc[mt][nt];
                    asm volatile(
                        "mma.sync.aligned.m16n8k16.row.col.f32.f16.f16.f32 "
                        "{%0,%1,%2,%3}, {%4,%5,%6,%7}, {%8,%9}, {%0,%1,%2,%3};"
                        : "+f"(d[0]), "+f"(d[1]), "+f"(d[2]), "+f"(d[3])
                        : "r"(a[mt][0]), "r"(a[mt][1]),
                          "r"(a[mt][2]), "r"(a[mt][3]),
                          "r"(b0), "r"(b1));
                }
            }
        }
        __syncthreads();
    }

    // ---- epilogue
    if (POOL) {
        // fused 2x2 maxpool; output fp16 cpair at (H/2, W/2)
        __half* out_h = reinterpret_cast<__half*>(out_raw);
        const int Ho = H >> 1, Wo = W >> 1;
        const size_t HWo = (size_t)Ho * Wo;
        #pragma unroll
        for (int mt = 0; mt < 2; ++mt) {
            int oc0 = oc_base + (warp_m * 2 + mt) * 16 + gid;
            float bv0 = bias[oc0];
            float bv1 = bias[oc0 + 8];
            #pragma unroll
            for (int g = 0; g < 2; ++g) {
                int nt  = g;
                int ntb = g + 2;
                float p0 = fmaxf(fmaxf(acc[mt][nt][0],  acc[mt][nt][1]),
                                 fmaxf(acc[mt][ntb][0], acc[mt][ntb][1]));
                float p1 = fmaxf(fmaxf(acc[mt][nt][2],  acc[mt][nt][3]),
                                 fmaxf(acc[mt][ntb][2], acc[mt][ntb][3]));
                p0 = fmaxf(p0 + bv0, 0.0f);
                p1 = fmaxf(p1 + bv1, 0.0f);
                int px = warp_n * 32 + nt * 8 + tig * 2;
                int oy = (by + (px >> 4)) >> 1;
                int ox = (bx + (px & 15)) >> 1;
                int ocA = oc0, ocB = oc0 + 8;
                out_h[(((size_t)(n_img * COUT + ocA) >> 1) * HWo
                       + (size_t)oy * Wo + ox) * 2 + (ocA & 1)] = __float2half_rn(p0);
                out_h[(((size_t)(n_img * COUT + ocB) >> 1) * HWo
                       + (size_t)oy * Wo + ox) * 2 + (ocB & 1)] = __float2half_rn(p1);
            }
        }
    } else if (ROUND) {
        // fp16 cpair output, same resolution
        __half* out_h = reinterpret_cast<__half*>(out_raw);
        #pragma unroll
        for (int mt = 0; mt < 2; ++mt) {
            int oc0 = oc_base + (warp_m * 2 + mt) * 16 + gid;
            float bv0 = bias[oc0];
            float bv1 = bias[oc0 + 8];
            #pragma unroll
            for (int nt = 0; nt < 4; ++nt) {
                int px = warp_n * 32 + nt * 8 + tig * 2;
                int gy = by + (px >> 4);
                int gx = bx + (px & 15);
                float v00 = fmaxf(acc[mt][nt][0] + bv0, 0.0f);
                float v01 = fmaxf(acc[mt][nt][1] + bv0, 0.0f);
                float v10 = fmaxf(acc[mt][nt][2] + bv1, 0.0f);
                float v11 = fmaxf(acc[mt][nt][3] + bv1, 0.0f);
                int ocA = oc0, ocB = oc0 + 8;
                size_t baseA = (((size_t)(n_img * COUT + ocA) >> 1) * HW
                                + (size_t)gy * W + gx) * 2 + (ocA & 1);
                size_t baseB = (((size_t)(n_img * COUT + ocB) >> 1) * HW
                                + (size_t)gy * W + gx) * 2 + (ocB & 1);
                out_h[baseA]     = __float2half_rn(v00);
                out_h[baseA + 2] = __float2half_rn(v01);
                out_h[baseB]     = __float2half_rn(v10);
                out_h[baseB + 2] = __float2half_rn(v11);
            }
        }
    } else {
        // final layer: fp32 NCHW
        float* out = reinterpret_cast<float*>(out_raw);
        #pragma unroll
        for (int mt = 0; mt < 2; ++mt) {
            int oc0 = oc_base + (warp_m * 2 + mt) * 16 + gid;
            float bv0 = bias[oc0];
            float bv1 = bias[oc0 + 8];
            #pragma unroll
            for (int nt = 0; nt < 4; ++nt) {
                int px = warp_n * 32 + nt * 8 + tig * 2;
                int gy = by + (px >> 4);
                int gx = bx + (px & 15);
                float v00 = fmaxf(acc[mt][nt][0] + bv0, 0.0f);
                float v01 = fmaxf(acc[mt][nt][1] + bv0, 0.0f);
                float v10 = fmaxf(acc[mt][nt][2] + bv1, 0.0f);
                float v11 = fmaxf(acc[mt][nt][3] + bv1, 0.0f);
                float* d0 = out + ((size_t)(n_img * COUT + oc0) * H + gy) * W + gx;
                float* d1 = d0 + (size_t)8 * HW;
                *reinterpret_cast<float2*>(d0) = make_float2(v00, v01);
                *reinterpret_cast<float2*>(d1) = make_float2(v10, v11);
            }
        }
    }
}

// ============================ FFMA2 conv (conv1 only) ======================
__device__ __forceinline__ unsigned long long fma2(unsigned long long a,
                                                   unsigned long long b,
                                                   unsigned long long c) {
    unsigned long long d;
    asm("fma.rn.f32x2 %0, %1, %2, %3;" : "=l"(d) : "l"(a), "l"(b), "l"(c));
    return d;
}
__device__ __forceinline__ unsigned long long dup2(float v) {
    unsigned long long d;
    asm("mov.b64 %0, {%1, %1};" : "=l"(d) : "f"(v));
    return d;
}
__device__ __forceinline__ float2 unpack2(unsigned long long v) {
    float2 r;
    asm("mov.b64 {%0, %1}, %2;" : "=f"(r.x), "=f"(r.y) : "l"(v));
    return r;
}
__device__ __host__ __forceinline__ int woff_of(int ocg) {
    return ocg * 8 + (ocg >> 2) * 2;
}

// conv1: 3->64 @384^2, fp32 in, fp16 cpair out.
template <int CIN, int COUT, int CHUNK, int TH, int TW>
__global__ void __launch_bounds__(256, 2)
conv3x3_ffma(const float* __restrict__ in,
             const float* __restrict__ wgt,
             const float* __restrict__ bias,
             __half* __restrict__ out, int H, int W)
{
    constexpr int OCB = 64;
    constexpr int WROW = 68;
    constexpr int IROW = TW + 2;
    constexpr int CG = TW / 8;

    __shared__ __align__(16) float wsm[CHUNK][9][WROW];
    __shared__ float insm[CHUNK][TH + 2][IROW];

    const int tiles_x = W / TW;
    const int bx = (blockIdx.x % tiles_x) * TW;
    const int by = (blockIdx.x / tiles_x) * TH;
    const int n  = blockIdx.y;
    const int oc_base = blockIdx.z * OCB;

    const int tid = threadIdx.x;
    const int ocg = tid & 7;
    const int pg  = tid >> 3;
    const int row = pg / CG;
    const int col = (pg % CG) * 8;
    const int woff = woff_of(ocg);

    unsigned long long acc[4][8];
    #pragma unroll
    for (int op = 0; op < 4; ++op)
        #pragma unroll
        for (int p = 0; p < 8; ++p) acc[op][p] = 0ull;

    #pragma unroll 1
    for (int c0 = 0; c0 < CIN; c0 += CHUNK) {
        {
            const float* wg = wgt + (size_t)oc_base * CIN * 9 + (size_t)c0 * 9;
            constexpr int PER_OC = CHUNK * 9;
            constexpr int TOT = OCB * PER_OC;
            for (int idx = tid; idx < TOT; idx += 256) {
                int oc = idx / PER_OC;
                int r  = idx % PER_OC;
                float v = wg[(size_t)oc * CIN * 9 + r];
                wsm[r / 9][r % 9][woff_of(oc >> 3) + (oc & 7)] = v;
            }
        }
        {
            constexpr int TILE2D = (TH + 2) * IROW;
            constexpr int TOT = CHUNK * TILE2D;
            for (int idx = tid; idx < TOT; idx += 256) {
                int c   = idx / TILE2D;
                int rem = idx % TILE2D;
                int iy  = rem / IROW;
                int ix  = rem % IROW;
                int gy = by + iy - 1;
                int gx = bx + ix - 1;
                float v = 0.0f;
                if (gy >= 0 && gy < H && gx >= 0 && gx < W)
                    v = in[(((size_t)n * CIN + c0 + c) * H + gy) * W + gx];
                insm[c][iy][ix] = v;
            }
        }
        __syncthreads();

        #pragma unroll 1
        for (int c = 0; c < CHUNK; ++c) {
            #pragma unroll
            for (int ky = 0; ky < 3; ++ky) {
                const float* rp = &insm[c][row + ky][col];
                unsigned long long d[10];
                #pragma unroll
                for (int i = 0; i < 10; ++i) d[i] = dup2(rp[i]);
                #pragma unroll
                for (int kx = 0; kx < 3; ++kx) {
                    const float* wp = &wsm[c][ky * 3 + kx][woff];
                    unsigned long long w2[4];
                    #pragma unroll
                    for (int j = 0; j < 4; ++j)
                        w2[j] = *reinterpret_cast<const unsigned long long*>(wp + 2 * j);
                    #pragma unroll
                    for (int op = 0; op < 4; ++op)
                        #pragma unroll
                        for (int p = 0; p < 8; ++p)
                            acc[op][p] = fma2(w2[op], d[kx + p], acc[op][p]);
                }
            }
        }
        __syncthreads();
    }

    // epilogue: bias+relu -> fp16 cpair ( (oc0, oc0+1) are a natural pair )
    const int gy = by + row;
    const int gx = bx + col;
    const size_t HW = (size_t)H * W;
    __half2* out_h2 = reinterpret_cast<__half2*>(out);
    #pragma unroll
    for (int op = 0; op < 4; ++op) {
        const int oc0 = oc_base + ocg * 8 + 2 * op;      // even
        const float b0 = bias[oc0];
        const float b1 = bias[oc0 + 1];
        size_t base = ((size_t)(n * COUT + oc0) >> 1) * HW + (size_t)gy * W + gx;
        #pragma unroll
        for (int p = 0; p < 8; ++p) {
            float2 u = unpack2(acc[op][p]);
            float lo = fmaxf(u.x + b0, 0.0f);
            float hi = fmaxf(u.y + b1, 0.0f);
            out_h2[base + p] = __floats2half2_rn(lo, hi);
        }
    }
}

// ============================ launchers ====================================
static constexpr int SMEM_MMA = (2 * 9 * 128) * 16 + 2 * (4 * 204 * 2) * 4; // 49920 B

template <int CIN, int COUT, bool ROUND, bool POOL>
static inline void launch_tconv(const void* in, const __half* wT, const float* b,
                                void* out, int H, int W, int N)
{
    cudaFuncSetAttribute(conv3x3_mma<CIN, COUT, ROUND, POOL>,
                         cudaFuncAttributeMaxDynamicSharedMemorySize, SMEM_MMA);
    dim3 grid((W / 16) * (H / 8), N, COUT / 64);
    conv3x3_mma<CIN, COUT, ROUND, POOL><<<grid, 256, SMEM_MMA>>>(
        (const __half*)in, wT, b, out, H, W);
}

extern "C" void kernel_launch(void* const* d_in, const int* in_sizes, int n_in,
                              void* d_out, int out_size)
{
    (void)in_sizes; (void)n_in; (void)out_size;

    const float* x = (const float*)d_in[0];          // (2,3,384,384)
    const float* w[11];
    const float* b[11];
    for (int k = 1; k <= 10; ++k) {
        w[k] = (const float*)d_in[2 + 2 * (k - 1)];
        b[k] = (const float*)d_in[3 + 2 * (k - 1)];
    }

    void* A;
    void* Bb;
    void* Wt;
    cudaGetSymbolAddress(&A,  g_bufA);
    cudaGetSymbolAddress(&Bb, g_bufB);
    cudaGetSymbolAddress(&Wt, g_bufW);
    __half* Wth = (__half*)Wt;
    const int N = 2;

    // ---- fused fragment-major fp16 transform of conv2..conv10 weights
    static const int CO[9] = {64, 128, 128, 256, 256, 256, 512, 512, 512};
    static const int CI[9] = {64,  64, 128, 128, 256, 256, 256, 512, 512};
    WXform p;
    long off = 0;
    for (int l = 0; l < 9; ++l) {
        p.src[l] = w[l + 2];
        p.cout[l] = CO[l];
        p.cin[l]  = CI[l];
        p.start[l] = off;
        off += (long)CO[l] * CI[l] * 9;
    }
    p.start[9] = off;
    {
        long blocks = (off + 255) / 256;
        transform_all<<<(unsigned)blocks, 256>>>(p, Wth);
    }

    // Stage 1 @ 384x384 — conv1 FFMA (fp16 cpair out), conv2 + fused pool
    {
        dim3 grid((384 / 32) * (384 / 8), N, 1);
        conv3x3_ffma<3, 64, 3, 8, 32><<<grid, 256>>>(x, w[1], b[1],
                                                     (__half*)A, 384, 384);
    }
    launch_tconv<64, 64, true, true>(A, Wth + p.start[0], b[2], Bb, 384, 384, N);

    // Stage 2 @ 192x192 — conv3, conv4 + fused pool -> 96^2
    launch_tconv<64, 128, true, false>(Bb, Wth + p.start[1], b[3], A, 192, 192, N);
    launch_tconv<128, 128, true, true>(A,  Wth + p.start[2], b[4], Bb, 192, 192, N);

    // Stage 3 @ 96x96 — conv5, conv6, conv7 + fused pool -> 48^2
    launch_tconv<128, 256, true, false>(Bb, Wth + p.start[3], b[5], A,  96, 96, N);
    launch_tconv<256, 256, true, false>(A,  Wth + p.start[4], b[6], Bb, 96, 96, N);
    launch_tconv<256, 256, true, true>(Bb,  Wth + p.start[5], b[7], A,  96, 96, N);

    // Stage 4 @ 48x48
    launch_tconv<256, 512, true, false>(A,  Wth + p.start[6], b[8],  Bb, 48, 48, N);
    launch_tconv<512, 512, true, false>(Bb, Wth + p.start[7], b[9],  A,  48, 48, N);
    launch_tconv<512, 512, false, false>(A, Wth + p.start[8], b[10], d_out, 48, 48, N);
}